// round 11
// baseline (speedup 1.0000x reference)
#include <cuda_runtime.h>
#include <cuda_fp16.h>
#include <cstdint>

#define N_ROWS 32768
#define D      64
#define K      1024
#define NTHR   256                     // 8 warps per CTA
#define ROWS_CTA 128
#define NBLK   (N_ROWS / ROWS_CTA)     // 256 CTAs (2/SM -> one wave)
#define NCH    64
#define NCHUNK (K / NCH)               // 16

#define OFF_QUANT 0
#define OFF_ENC   ((size_t)N_ROWS * D)
#define OFF_IDX   (OFF_ENC + (size_t)N_ROWS * K)
#define OFF_LOSS  (OFF_IDX + (size_t)N_ROWS)

// smem (floats): esq[1024] | buf0[5120] | buf1[5120] | xtile[128*68] | wl[8]
#define SMF_ESQ  0
#define SMF_BUF  1024
#define SMF_X    (1024 + 10240)
#define XSTRIDE  68
#define SMF_WL   (SMF_X + 128 * XSTRIDE)
#define SMEM_SZ  ((SMF_WL + 8) * 4)              // 79904 B -> 2 CTAs/SM

// Packed per-chunk B block (20KB each, 16 chunks):
//   u4[   0..255]  hi ks0|ks1   [nt(8)][lane(32)] -> uint4
//   u4[ 256..511]  lo ks0|ks1
//   u4[ 512..767]  hi ks2|ks3
//   u4[ 768..1023] lo ks2|ks3
//   u2[2048..2303] hi ks4 (esq pseudo-dim)   (byte 16384)
//   u2[2304..2559] lo ks4                    (byte 18432)
__device__ uint4 g_bpk[NCHUNK * 1280];
__device__ float g_et [K * D];           // exact emb^T [k][d]
__device__ float g_esq[K];
__device__ unsigned long long g_loss;
__device__ unsigned int g_done;          // wraps to 0 each launch (atomicInc)

__device__ __forceinline__ uint32_t smem_u32(const void* p) {
    uint32_t a;
    asm("{ .reg .u64 t; cvta.to.shared.u64 t, %1; cvt.u32.u64 %0, t; }"
        : "=r"(a) : "l"(p));
    return a;
}
__device__ __forceinline__ uint32_t packh2(float a, float b) {
    __half2 h = __floats2half2_rn(a, b);   // a -> low half (smaller index)
    return *(uint32_t*)&h;
}

#define CP16(dst, src) asm volatile( \
    "cp.async.cg.shared.global [%0], [%1], 16;" :: "r"(dst), "l"(src) : "memory")
#define CP_COMMIT() asm volatile("cp.async.commit_group;" ::: "memory")
#define CP_WAIT0()  asm volatile("cp.async.wait_group 0;" ::: "memory")

#define LDS64(r0, r1, addr) asm volatile( \
    "ld.shared.v2.b32 {%0,%1}, [%2];" : "=r"(r0), "=r"(r1) : "r"(addr))
#define LDS128(r0, r1, r2, r3, addr) asm volatile( \
    "ld.shared.v4.b32 {%0,%1,%2,%3}, [%4];" \
    : "=r"(r0), "=r"(r1), "=r"(r2), "=r"(r3) : "r"(addr))

#define MMAF16(Cp, Ap, B0, B1) asm volatile( \
    "mma.sync.aligned.m16n8k16.row.col.f32.f16.f16.f32 " \
    "{%0,%1,%2,%3},{%4,%5,%6,%7},{%8,%9},{%0,%1,%2,%3};" \
    : "+f"((Cp)[0]), "+f"((Cp)[1]), "+f"((Cp)[2]), "+f"((Cp)[3]) \
    : "r"((Ap)[0]), "r"((Ap)[1]), "r"((Ap)[2]), "r"((Ap)[3]), \
      "r"(B0), "r"(B1))

// ---------------- prep: e^T, ||e||^2, packed fp16 hi/lo fragments ----------
__global__ void prep_all(const float* __restrict__ emb) {
    int idx = blockIdx.x * blockDim.x + threadIdx.x;   // 0..4095
    if (idx == 0) g_loss = 0ull;
    int lane = idx & 31;
    int ntg  = idx >> 5;                 // 0..127 global n-tile
    int c    = ntg >> 3, nt = ntg & 7;
    int cw   = ntg * 8 + (lane >> 2);

    // exact esq for this cw (4x redundant across lane&3; cheap)
    float esq = 0.f;
    #pragma unroll
    for (int d = 0; d < D; d++) {
        float v = emb[d * K + cw];
        esq = fmaf(v, v, esq);
    }

    uint32_t h[4], l[4];   // ks0..ks3 frags (2 u32 each -> pack pairwise)
    uint4 out4;
    #pragma unroll
    for (int ks = 0; ks < 4; ks++) {
        int d0 = ks * 16 + (lane & 3) * 2;
        float v0 = emb[(d0    ) * K + cw];
        float v1 = emb[(d0 + 1) * K + cw];
        float v2 = emb[(d0 + 8) * K + cw];
        float v3 = emb[(d0 + 9) * K + cw];
        float h0 = __half2float(__float2half_rn(v0));
        float h1 = __half2float(__float2half_rn(v1));
        float h2 = __half2float(__float2half_rn(v2));
        float h3 = __half2float(__float2half_rn(v3));
        h[ks]     = 0; l[ks] = 0;  // placeholders (unused)
        uint32_t hu0 = packh2(h0, h1), hu1 = packh2(h2, h3);
        uint32_t lu0 = packh2(v0 - h0, v1 - h1), lu1 = packh2(v2 - h2, v3 - h3);
        int slot = c * 1280 + (ks >> 1) * 512 + nt * 32 + lane;
        if ((ks & 1) == 0) {
            out4.x = hu0; out4.y = hu1;
            g_bpk[slot + 256].x = lu0; g_bpk[slot + 256].y = lu1;
        } else {
            out4.z = hu0; out4.w = hu1;
            uint4 lo4 = g_bpk[slot + 256];
            lo4.z = lu0; lo4.w = lu1;
            g_bpk[slot + 256] = lo4;
            g_bpk[slot] = out4;
        }
    }
    // ks4: esq pseudo-dim (d64 = esq, rest 0); only lane&3 == 0 holds it
    {
        float eh = __half2float(__float2half_rn(esq));
        float el = esq - eh;
        uint2 hv = make_uint2(0, 0), lv = make_uint2(0, 0);
        if ((lane & 3) == 0) {
            hv.x = packh2(eh, 0.f);
            lv.x = packh2(el, 0.f);
        }
        uint2* p2 = (uint2*)g_bpk;
        p2[c * 2560 + 2048 + nt * 32 + lane] = hv;
        p2[c * 2560 + 2304 + nt * 32 + lane] = lv;
    }
    // exact transpose + norms (first 1024 threads)
    if (idx < K) {
        float s = 0.f;
        #pragma unroll
        for (int d = 0; d < D; d++) {
            float v = emb[d * K + idx];
            g_et[idx * D + d] = v;
            s = fmaf(v, v, s);
        }
        g_esq[idx] = s;
    }
}

// ---------------- staging: 20KB linear copy per chunk ----------------------
__device__ __forceinline__ void stage_chunk(uint32_t bufb, int c, int tid) {
    const char* s = (const char*)(g_bpk + (size_t)c * 1280);
    #pragma unroll
    for (int i = 0; i < 5; i++) {
        uint32_t o = (uint32_t)(i * NTHR + tid) * 16;
        CP16(bufb + o, s + o);
    }
    CP_COMMIT();
}

__device__ __forceinline__ bool sless(float s, int i, float S, int I) {
    return (s < S) || (s == S && i < I);
}

// ---------------- main ------------------------------------------------------
__global__ __launch_bounds__(NTHR, 2) void vq_mma(const float* __restrict__ x,
                                                  float* __restrict__ out) {
    extern __shared__ __align__(16) float smem[];
    const uint32_t smb = smem_u32(smem);
    float* esq_s = smem + SMF_ESQ;
    float* xs    = smem + SMF_X;
    const int tid  = threadIdx.x;
    const int wid  = tid >> 5, lane = tid & 31;
    const int r0   = lane >> 2, c0 = lane & 3;
    const int rowbase = blockIdx.x * ROWS_CTA;

    stage_chunk(smb + SMF_BUF * 4, 0, tid);

    #pragma unroll
    for (int i = 0; i < K / NTHR; i++)
        esq_s[i * NTHR + tid] = g_esq[i * NTHR + tid];

    // stage x tile (raw floats, stride 68 => conflict-free row reads)
    {
        const float4* xg = (const float4*)(x + (size_t)rowbase * D);
        #pragma unroll
        for (int i = 0; i < 8; i++) {
            int idx = i * NTHR + tid;
            int r = idx >> 4, d4 = idx & 15;
            *(float4*)(xs + r * XSTRIDE + d4 * 4) = xg[idx];
        }
    }
    __syncthreads();

    // A fragments: y = -2x, split y = y0 + y1 (fp16); +ks4 pseudo-dim (y=1).
    uint32_t ay0[20], ay1[16];
    #pragma unroll
    for (int ks = 0; ks < 4; ks++)
        #pragma unroll
        for (int p = 0; p < 4; p++) {
            int r = wid * 16 + r0 + (p & 1) * 8;
            int d = ks * 16 + c0 * 2 + (p >> 1) * 8;
            float va = -2.f * xs[r * XSTRIDE + d];
            float vb = -2.f * xs[r * XSTRIDE + d + 1];
            float ha = __half2float(__float2half_rn(va));
            float hb = __half2float(__float2half_rn(vb));
            ay0[ks * 4 + p] = packh2(ha, hb);
            ay1[ks * 4 + p] = packh2(va - ha, vb - hb);
        }
    {
        uint32_t one = (c0 == 0) ? packh2(1.f, 0.f) : 0u;
        ay0[16] = one; ay0[17] = one; ay0[18] = 0u; ay0[19] = 0u;
    }

    // per-slot exact top-2; slot 0 = row r0, slot 1 = row r0+8
    float s1[2], s2[2];
    int   i1[2], i2[2];
    #pragma unroll
    for (int s = 0; s < 2; s++) { s1[s] = s2[s] = 3.4e38f; i1[s] = i2[s] = 0; }

    #pragma unroll 1
    for (int c = 0; c < NCHUNK; c++) {
        CP_WAIT0();
        __syncthreads();   // buf[c] visible; prior reads of other buf done
        if (c + 1 < NCHUNK)
            stage_chunk(smb + (SMF_BUF + ((c + 1) & 1) * 5120) * 4, c + 1, tid);

        // encodings zero-fill for this chunk's 64 columns
        {
            float4 z = make_float4(0.f, 0.f, 0.f, 0.f);
            float* enc = out + OFF_ENC + (size_t)rowbase * K + (size_t)c * NCH;
            #pragma unroll
            for (int j = 0; j < 8; j++) {
                int idx = j * NTHR + tid;
                *(float4*)(enc + (size_t)(idx >> 4) * K + (idx & 15) * 4) = z;
            }
        }

        const uint32_t bufb = smb + (SMF_BUF + (c & 1) * 5120) * 4;

        #pragma unroll
        for (int nt = 0; nt < 8; nt++) {
            uint32_t ha, hb, hc, hd, la, lb, lc, ld;
            uint32_t h2a, h2b, h2c, h2d, l2a, l2b, l2c, l2d;
            uint32_t h4a, h4b, l4a, l4b;
            uint32_t base16 = bufb + (uint32_t)((nt * 32 + lane) * 16);
            uint32_t base8  = bufb + (uint32_t)((nt * 32 + lane) * 8);
            LDS128(ha, hb, hc, hd, base16);              // hi ks0|ks1
            LDS128(la, lb, lc, ld, base16 + 4096);       // lo ks0|ks1
            LDS128(h2a, h2b, h2c, h2d, base16 + 8192);   // hi ks2|ks3
            LDS128(l2a, l2b, l2c, l2d, base16 + 12288);  // lo ks2|ks3
            LDS64(h4a, h4b, base8 + 16384);              // hi ks4
            LDS64(l4a, l4b, base8 + 18432);              // lo ks4

            float C[4] = {0.f, 0.f, 0.f, 0.f};
            MMAF16(C, ay0 + 0,  ha,  hb);   // ks0: y0*e0
            MMAF16(C, ay1 + 0,  ha,  hb);   //      y1*e0
            MMAF16(C, ay0 + 0,  la,  lb);   //      y0*e1
            MMAF16(C, ay0 + 4,  hc,  hd);   // ks1
            MMAF16(C, ay1 + 4,  hc,  hd);
            MMAF16(C, ay0 + 4,  lc,  ld);
            MMAF16(C, ay0 + 8,  h2a, h2b);  // ks2
            MMAF16(C, ay1 + 8,  h2a, h2b);
            MMAF16(C, ay0 + 8,  l2a, l2b);
            MMAF16(C, ay0 + 12, h2c, h2d);  // ks3
            MMAF16(C, ay1 + 12, h2c, h2d);
            MMAF16(C, ay0 + 12, l2c, l2d);
            MMAF16(C, ay0 + 16, h4a, h4b);  // ks4 (esq): y0*e0
            MMAF16(C, ay0 + 16, l4a, l4b);  //            y0*e1

            // exact pair-then-insert top-2 (cols ascending, strict <)
            int cb = c * NCH + nt * 8 + c0 * 2;
            {
                float m = fminf(C[0], C[1]);
                int  mc = cb + ((C[1] < C[0]) ? 1 : 0);
                bool p1 = m < s1[0], p2 = m < s2[0];
                s2[0] = p1 ? s1[0] : (p2 ? m : s2[0]);
                i2[0] = p1 ? i1[0] : (p2 ? mc : i2[0]);
                i1[0] = p1 ? mc : i1[0];
                s1[0] = p1 ? m  : s1[0];
            }
            {
                float m = fminf(C[2], C[3]);
                int  mc = cb + ((C[3] < C[2]) ? 1 : 0);
                bool p1 = m < s1[1], p2 = m < s2[1];
                s2[1] = p1 ? s1[1] : (p2 ? m : s2[1]);
                i2[1] = p1 ? i1[1] : (p2 ? mc : i2[1]);
                i1[1] = p1 ? mc : i1[1];
                s1[1] = p1 ? m  : s1[1];
            }
        }
    }

    // quad-merge top-2 across the 4 lanes sharing each row
    #pragma unroll
    for (int sl = 0; sl < 2; sl++) {
        #pragma unroll
        for (int off = 1; off <= 2; off <<= 1) {
            float os1 = __shfl_xor_sync(0xFFFFFFFF, s1[sl], off);
            int   oi1 = __shfl_xor_sync(0xFFFFFFFF, i1[sl], off);
            float os2 = __shfl_xor_sync(0xFFFFFFFF, s2[sl], off);
            int   oi2 = __shfl_xor_sync(0xFFFFFFFF, i2[sl], off);
            if (sless(os1, oi1, s1[sl], i1[sl])) {
                if (sless(s1[sl], i1[sl], os2, oi2)) {
                    s2[sl] = s1[sl]; i2[sl] = i1[sl];
                } else {
                    s2[sl] = os2; i2[sl] = oi2;
                }
                s1[sl] = os1; i1[sl] = oi1;
            } else if (sless(os1, oi1, s2[sl], i2[sl])) {
                s2[sl] = os1; i2[sl] = oi1;
            }
        }
    }
    int2* rowtab = (int2*)(smem + SMF_BUF);   // buf0 free now (last read: c=14)
    if (c0 == 0) {
        #pragma unroll
        for (int sl = 0; sl < 2; sl++)
            rowtab[wid * 16 + sl * 8 + r0] = make_int2(i1[sl], i2[sl]);
    }
    __syncthreads();

    // final per-row epilogue (threads 0..127): exact fp32 rescore of top-2
    long long* wl = (long long*)(smem + SMF_WL);
    if (tid < ROWS_CTA) {
        const int row = rowbase + tid;
        int ca = rowtab[tid].x, cb2 = rowtab[tid].y;
        const float4* xp = (const float4*)(xs + tid * XSTRIDE);
        float da = 0.f, db = 0.f;
        {
            const float4* ea = (const float4*)(g_et + (size_t)ca * D);
            const float4* eb = (const float4*)(g_et + (size_t)cb2 * D);
            #pragma unroll
            for (int i = 0; i < 16; i++) {
                float4 xv = xp[i], e1v = ea[i], e2v = eb[i];
                da = fmaf(xv.x, e1v.x, da); da = fmaf(xv.y, e1v.y, da);
                da = fmaf(xv.z, e1v.z, da); da = fmaf(xv.w, e1v.w, da);
                db = fmaf(xv.x, e2v.x, db); db = fmaf(xv.y, e2v.y, db);
                db = fmaf(xv.z, e2v.z, db); db = fmaf(xv.w, e2v.w, db);
            }
        }
        float sa = fmaf(-2.f, da, esq_s[ca]);
        float sb = fmaf(-2.f, db, esq_s[cb2]);
        int bi = sless(sb, cb2, sa, ca) ? cb2 : ca;

        float ls = 0.f;
        {
            const float4* ep = (const float4*)(g_et + (size_t)bi * D);
            float4* qp = (float4*)(out + OFF_QUANT + (size_t)row * D);
            #pragma unroll
            for (int i = 0; i < 16; i++) {
                float4 e = ep[i], xv = xp[i];
                qp[i] = e;
                float a0 = e.x - xv.x, a1 = e.y - xv.y;
                float a2 = e.z - xv.z, a3 = e.w - xv.w;
                ls = fmaf(a0, a0, ls); ls = fmaf(a1, a1, ls);
                ls = fmaf(a2, a2, ls); ls = fmaf(a3, a3, ls);
            }
        }
        #pragma unroll
        for (int off = 16; off > 0; off >>= 1)
            ls += __shfl_xor_sync(0xFFFFFFFF, ls, off);
        if (lane == 0)   // fixed-point warp partial -> smem (deterministic)
            wl[wid] = (long long)__float2ll_rn(ls * 16777216.0f);

        out[OFF_IDX + row] = (float)bi;
        out[OFF_ENC + (size_t)row * K + bi] = 1.0f;
    }
    __syncthreads();

    // tid 0: single fenced g_loss add, then last-CTA-done finalize
    if (tid == 0) {
        long long csum = wl[0] + wl[1] + wl[2] + wl[3];
        atomicAdd(&g_loss, (unsigned long long)csum);
        __threadfence();
        unsigned int old = atomicInc(&g_done, NBLK - 1);
        if (old == NBLK - 1) {
            unsigned long long tot = atomicAdd(&g_loss, 0ull);
            out[OFF_LOSS] = (float)((double)tot
                          / (16777216.0 * (double)N_ROWS * (double)D));
        }
    }
}

extern "C" void kernel_launch(void* const* d_in, const int* in_sizes, int n_in,
                              void* d_out, int out_size) {
    const float* x   = (const float*)d_in[0];   // [8,4096,64]
    const float* emb = (const float*)d_in[1];   // [64,1024]
    float* out = (float*)d_out;

    cudaFuncSetAttribute(vq_mma, cudaFuncAttributeMaxDynamicSharedMemorySize,
                         SMEM_SZ);
    prep_all<<<16, 256>>>(emb);
    vq_mma<<<NBLK, NTHR, SMEM_SZ>>>(x, out);
}

// round 12
// speedup vs baseline: 1.0473x; 1.0473x over previous
#include <cuda_runtime.h>
#include <cuda_fp16.h>
#include <cstdint>

#define N_ROWS 32768
#define D      64
#define K      1024
#define NTHR   256                     // 8 warps per CTA
#define ROWS_CTA 128
#define NBLK   (N_ROWS / ROWS_CTA)     // 256 CTAs (2/SM -> one wave)
#define NCH    64
#define NCHUNK (K / NCH)               // 16

#define OFF_QUANT 0
#define OFF_ENC   ((size_t)N_ROWS * D)
#define OFF_IDX   (OFF_ENC + (size_t)N_ROWS * K)
#define OFF_LOSS  (OFF_IDX + (size_t)N_ROWS)

// smem (floats): esq[1024] | buf0[5120] | buf1[5120] | xtile[128*68] | wl[8]
#define SMF_ESQ  0
#define SMF_BUF  1024
#define SMF_X    (1024 + 10240)
#define XSTRIDE  68
#define SMF_WL   (SMF_X + 128 * XSTRIDE)
#define SMEM_SZ  ((SMF_WL + 8) * 4)              // 79904 B -> 2 CTAs/SM

// Packed per-chunk B block (20KB each, 16 chunks):
//   u4[   0..255]  hi ks0|ks1   [nt(8)][lane(32)] -> uint4
//   u4[ 256..511]  lo ks0|ks1
//   u4[ 512..767]  hi ks2|ks3
//   u4[ 768..1023] lo ks2|ks3
//   u2[2048..2303] hi ks4 (esq pseudo-dim)   (byte 16384)
//   u2[2304..2559] lo ks4                    (byte 18432)
__device__ uint4 g_bpk[NCHUNK * 1280];
__device__ float g_et [K * D];           // exact emb^T [k][d]
__device__ float g_esq[K];
__device__ unsigned long long g_loss;
__device__ unsigned int g_done;          // wraps to 0 each launch (atomicInc)

__device__ __forceinline__ uint32_t smem_u32(const void* p) {
    uint32_t a;
    asm("{ .reg .u64 t; cvta.to.shared.u64 t, %1; cvt.u32.u64 %0, t; }"
        : "=r"(a) : "l"(p));
    return a;
}
__device__ __forceinline__ uint32_t packh2(float a, float b) {
    __half2 h = __floats2half2_rn(a, b);   // a -> low half (smaller index)
    return *(uint32_t*)&h;
}

#define CP16(dst, src) asm volatile( \
    "cp.async.cg.shared.global [%0], [%1], 16;" :: "r"(dst), "l"(src) : "memory")
#define CP_COMMIT() asm volatile("cp.async.commit_group;" ::: "memory")
#define CP_WAIT0()  asm volatile("cp.async.wait_group 0;" ::: "memory")

#define LDS64(r0, r1, addr) asm volatile( \
    "ld.shared.v2.b32 {%0,%1}, [%2];" : "=r"(r0), "=r"(r1) : "r"(addr))
#define LDS128(r0, r1, r2, r3, addr) asm volatile( \
    "ld.shared.v4.b32 {%0,%1,%2,%3}, [%4];" \
    : "=r"(r0), "=r"(r1), "=r"(r2), "=r"(r3) : "r"(addr))

#define MMAF16(Cp, Ap, B0, B1) asm volatile( \
    "mma.sync.aligned.m16n8k16.row.col.f32.f16.f16.f32 " \
    "{%0,%1,%2,%3},{%4,%5,%6,%7},{%8,%9},{%0,%1,%2,%3};" \
    : "+f"((Cp)[0]), "+f"((Cp)[1]), "+f"((Cp)[2]), "+f"((Cp)[3]) \
    : "r"((Ap)[0]), "r"((Ap)[1]), "r"((Ap)[2]), "r"((Ap)[3]), \
      "r"(B0), "r"(B1))

// ---------------- prep: e^T, ||e||^2, packed fp16 hi/lo fragments ----------
// 4096 threads; all stores assembled in registers (no global RMW).
__global__ void prep_all(const float* __restrict__ emb) {
    int idx = blockIdx.x * blockDim.x + threadIdx.x;   // 0..4095
    if (idx == 0) g_loss = 0ull;
    int lane = idx & 31;
    int ntg  = idx >> 5;                 // 0..127 global n-tile
    int c    = ntg >> 3, nt = ntg & 7;
    int cw   = ntg * 8 + (lane >> 2);

    uint4 hi01, lo01, hi23, lo23;
    #pragma unroll
    for (int ks = 0; ks < 4; ks++) {
        int d0 = ks * 16 + (lane & 3) * 2;
        float v0 = emb[(d0    ) * K + cw];
        float v1 = emb[(d0 + 1) * K + cw];
        float v2 = emb[(d0 + 8) * K + cw];
        float v3 = emb[(d0 + 9) * K + cw];
        float h0 = __half2float(__float2half_rn(v0));
        float h1 = __half2float(__float2half_rn(v1));
        float h2 = __half2float(__float2half_rn(v2));
        float h3 = __half2float(__float2half_rn(v3));
        uint32_t hu0 = packh2(h0, h1), hu1 = packh2(h2, h3);
        uint32_t lu0 = packh2(v0 - h0, v1 - h1), lu1 = packh2(v2 - h2, v3 - h3);
        if (ks == 0)      { hi01.x = hu0; hi01.y = hu1; lo01.x = lu0; lo01.y = lu1; }
        else if (ks == 1) { hi01.z = hu0; hi01.w = hu1; lo01.z = lu0; lo01.w = lu1; }
        else if (ks == 2) { hi23.x = hu0; hi23.y = hu1; lo23.x = lu0; lo23.y = lu1; }
        else              { hi23.z = hu0; hi23.w = hu1; lo23.z = lu0; lo23.w = lu1; }
    }
    int slot = c * 1280 + nt * 32 + lane;
    g_bpk[slot        ] = hi01;
    g_bpk[slot +  256 ] = lo01;
    g_bpk[slot +  512 ] = hi23;
    g_bpk[slot +  768 ] = lo23;

    // ks4: esq pseudo-dim; only lane&3==0 carries data (d-col 0 of the frag)
    {
        uint2 hv = make_uint2(0, 0), lv = make_uint2(0, 0);
        if ((lane & 3) == 0) {
            float esq = 0.f;
            #pragma unroll
            for (int d = 0; d < D; d++) {
                float v = emb[d * K + cw];
                esq = fmaf(v, v, esq);
            }
            float eh = __half2float(__float2half_rn(esq));
            hv.x = packh2(eh, 0.f);
            lv.x = packh2(esq - eh, 0.f);
        }
        uint2* p2 = (uint2*)g_bpk;
        p2[c * 2560 + 2048 + nt * 32 + lane] = hv;
        p2[c * 2560 + 2304 + nt * 32 + lane] = lv;
    }
    // exact transpose + norms (first 1024 threads)
    if (idx < K) {
        float s = 0.f;
        #pragma unroll
        for (int d = 0; d < D; d++) {
            float v = emb[d * K + idx];
            g_et[idx * D + d] = v;
            s = fmaf(v, v, s);
        }
        g_esq[idx] = s;
    }
}

// ---------------- staging: 20KB linear copy per chunk ----------------------
__device__ __forceinline__ void stage_chunk(uint32_t bufb, int c, int tid) {
    const char* s = (const char*)(g_bpk + (size_t)c * 1280);
    #pragma unroll
    for (int i = 0; i < 5; i++) {
        uint32_t o = (uint32_t)(i * NTHR + tid) * 16;
        CP16(bufb + o, s + o);
    }
    CP_COMMIT();
}

__device__ __forceinline__ bool sless(float s, int i, float S, int I) {
    return (s < S) || (s == S && i < I);
}

// ---------------- main ------------------------------------------------------
__global__ __launch_bounds__(NTHR, 2) void vq_mma(const float* __restrict__ x,
                                                  float* __restrict__ out) {
    extern __shared__ __align__(16) float smem[];
    const uint32_t smb = smem_u32(smem);
    float* esq_s = smem + SMF_ESQ;
    float* xs    = smem + SMF_X;
    const int tid  = threadIdx.x;
    const int wid  = tid >> 5, lane = tid & 31;
    const int r0   = lane >> 2, c0 = lane & 3;
    const int rowbase = blockIdx.x * ROWS_CTA;

    stage_chunk(smb + SMF_BUF * 4, 0, tid);

    #pragma unroll
    for (int i = 0; i < K / NTHR; i++)
        esq_s[i * NTHR + tid] = g_esq[i * NTHR + tid];

    // stage x tile (raw floats, stride 68 => conflict-free row reads)
    {
        const float4* xg = (const float4*)(x + (size_t)rowbase * D);
        #pragma unroll
        for (int i = 0; i < 8; i++) {
            int idx = i * NTHR + tid;
            int r = idx >> 4, d4 = idx & 15;
            *(float4*)(xs + r * XSTRIDE + d4 * 4) = xg[idx];
        }
    }
    __syncthreads();

    // A fragments: y = -2x, split y = y0 + y1 (fp16); +ks4 pseudo-dim (y=1).
    uint32_t ay0[20], ay1[16];
    #pragma unroll
    for (int ks = 0; ks < 4; ks++)
        #pragma unroll
        for (int p = 0; p < 4; p++) {
            int r = wid * 16 + r0 + (p & 1) * 8;
            int d = ks * 16 + c0 * 2 + (p >> 1) * 8;
            float va = -2.f * xs[r * XSTRIDE + d];
            float vb = -2.f * xs[r * XSTRIDE + d + 1];
            float ha = __half2float(__float2half_rn(va));
            float hb = __half2float(__float2half_rn(vb));
            ay0[ks * 4 + p] = packh2(ha, hb);
            ay1[ks * 4 + p] = packh2(va - ha, vb - hb);
        }
    {
        uint32_t one = (c0 == 0) ? packh2(1.f, 0.f) : 0u;
        ay0[16] = one; ay0[17] = one; ay0[18] = 0u; ay0[19] = 0u;
    }

    // per-slot exact top-2; slot 0 = row r0, slot 1 = row r0+8
    float s1[2], s2[2];
    int   i1[2], i2[2];
    #pragma unroll
    for (int s = 0; s < 2; s++) { s1[s] = s2[s] = 3.4e38f; i1[s] = i2[s] = 0; }

    #pragma unroll 1
    for (int c = 0; c < NCHUNK; c++) {
        CP_WAIT0();
        __syncthreads();   // buf[c] visible; prior reads of other buf done
        if (c + 1 < NCHUNK)
            stage_chunk(smb + (SMF_BUF + ((c + 1) & 1) * 5120) * 4, c + 1, tid);

        // encodings zero-fill for this chunk's 64 columns
        {
            float4 z = make_float4(0.f, 0.f, 0.f, 0.f);
            float* enc = out + OFF_ENC + (size_t)rowbase * K + (size_t)c * NCH;
            #pragma unroll
            for (int j = 0; j < 8; j++) {
                int idx = j * NTHR + tid;
                *(float4*)(enc + (size_t)(idx >> 4) * K + (idx & 15) * 4) = z;
            }
        }

        const uint32_t bufb = smb + (SMF_BUF + (c & 1) * 5120) * 4;

        // nt pairs: two independent accumulator chains (2-way MMA ILP)
        #pragma unroll
        for (int nt = 0; nt < 8; nt += 2) {
            uint32_t Ah01[4], Al01[4], Ah23[4], Al23[4], Ah4[2], Al4[2];
            uint32_t Bh01[4], Bl01[4], Bh23[4], Bl23[4], Bh4[2], Bl4[2];
            {
                uint32_t a16 = bufb + (uint32_t)(((nt    ) * 32 + lane) * 16);
                uint32_t b16 = bufb + (uint32_t)(((nt + 1) * 32 + lane) * 16);
                uint32_t a8  = bufb + (uint32_t)(((nt    ) * 32 + lane) * 8);
                uint32_t b8  = bufb + (uint32_t)(((nt + 1) * 32 + lane) * 8);
                LDS128(Ah01[0], Ah01[1], Ah01[2], Ah01[3], a16);
                LDS128(Bh01[0], Bh01[1], Bh01[2], Bh01[3], b16);
                LDS128(Al01[0], Al01[1], Al01[2], Al01[3], a16 + 4096);
                LDS128(Bl01[0], Bl01[1], Bl01[2], Bl01[3], b16 + 4096);
                LDS128(Ah23[0], Ah23[1], Ah23[2], Ah23[3], a16 + 8192);
                LDS128(Bh23[0], Bh23[1], Bh23[2], Bh23[3], b16 + 8192);
                LDS128(Al23[0], Al23[1], Al23[2], Al23[3], a16 + 12288);
                LDS128(Bl23[0], Bl23[1], Bl23[2], Bl23[3], b16 + 12288);
                LDS64(Ah4[0], Ah4[1], a8 + 16384);
                LDS64(Bh4[0], Bh4[1], b8 + 16384);
                LDS64(Al4[0], Al4[1], a8 + 18432);
                LDS64(Bl4[0], Bl4[1], b8 + 18432);
            }
            float C0[4] = {0.f, 0.f, 0.f, 0.f};
            float C1[4] = {0.f, 0.f, 0.f, 0.f};
            // alternate chains: consecutive MMAs are independent
            MMAF16(C0, ay0 + 0,  Ah01[0], Ah01[1]);
            MMAF16(C1, ay0 + 0,  Bh01[0], Bh01[1]);
            MMAF16(C0, ay1 + 0,  Ah01[0], Ah01[1]);
            MMAF16(C1, ay1 + 0,  Bh01[0], Bh01[1]);
            MMAF16(C0, ay0 + 0,  Al01[0], Al01[1]);
            MMAF16(C1, ay0 + 0,  Bl01[0], Bl01[1]);
            MMAF16(C0, ay0 + 4,  Ah01[2], Ah01[3]);
            MMAF16(C1, ay0 + 4,  Bh01[2], Bh01[3]);
            MMAF16(C0, ay1 + 4,  Ah01[2], Ah01[3]);
            MMAF16(C1, ay1 + 4,  Bh01[2], Bh01[3]);
            MMAF16(C0, ay0 + 4,  Al01[2], Al01[3]);
            MMAF16(C1, ay0 + 4,  Bl01[2], Bl01[3]);
            MMAF16(C0, ay0 + 8,  Ah23[0], Ah23[1]);
            MMAF16(C1, ay0 + 8,  Bh23[0], Bh23[1]);
            MMAF16(C0, ay1 + 8,  Ah23[0], Ah23[1]);
            MMAF16(C1, ay1 + 8,  Bh23[0], Bh23[1]);
            MMAF16(C0, ay0 + 8,  Al23[0], Al23[1]);
            MMAF16(C1, ay0 + 8,  Bl23[0], Bl23[1]);
            MMAF16(C0, ay0 + 12, Ah23[2], Ah23[3]);
            MMAF16(C1, ay0 + 12, Bh23[2], Bh23[3]);
            MMAF16(C0, ay1 + 12, Ah23[2], Ah23[3]);
            MMAF16(C1, ay1 + 12, Bh23[2], Bh23[3]);
            MMAF16(C0, ay0 + 12, Al23[2], Al23[3]);
            MMAF16(C1, ay0 + 12, Bl23[2], Bl23[3]);
            MMAF16(C0, ay0 + 16, Ah4[0],  Ah4[1]);   // ks4 (esq)
            MMAF16(C1, ay0 + 16, Bh4[0],  Bh4[1]);
            MMAF16(C0, ay0 + 16, Al4[0],  Al4[1]);
            MMAF16(C1, ay0 + 16, Bl4[0],  Bl4[1]);

            // exact pair-then-insert top-2 (cols ascending, strict <)
            int cbA = c * NCH + nt * 8 + c0 * 2;
            int cbB = cbA + 8;
            {
                float m = fminf(C0[0], C0[1]);
                int  mc = cbA + ((C0[1] < C0[0]) ? 1 : 0);
                bool p1 = m < s1[0], p2 = m < s2[0];
                s2[0] = p1 ? s1[0] : (p2 ? m : s2[0]);
                i2[0] = p1 ? i1[0] : (p2 ? mc : i2[0]);
                i1[0] = p1 ? mc : i1[0];
                s1[0] = p1 ? m  : s1[0];
            }
            {
                float m = fminf(C0[2], C0[3]);
                int  mc = cbA + ((C0[3] < C0[2]) ? 1 : 0);
                bool p1 = m < s1[1], p2 = m < s2[1];
                s2[1] = p1 ? s1[1] : (p2 ? m : s2[1]);
                i2[1] = p1 ? i1[1] : (p2 ? mc : i2[1]);
                i1[1] = p1 ? mc : i1[1];
                s1[1] = p1 ? m  : s1[1];
            }
            {
                float m = fminf(C1[0], C1[1]);
                int  mc = cbB + ((C1[1] < C1[0]) ? 1 : 0);
                bool p1 = m < s1[0], p2 = m < s2[0];
                s2[0] = p1 ? s1[0] : (p2 ? m : s2[0]);
                i2[0] = p1 ? i1[0] : (p2 ? mc : i2[0]);
                i1[0] = p1 ? mc : i1[0];
                s1[0] = p1 ? m  : s1[0];
            }
            {
                float m = fminf(C1[2], C1[3]);
                int  mc = cbB + ((C1[3] < C1[2]) ? 1 : 0);
                bool p1 = m < s1[1], p2 = m < s2[1];
                s2[1] = p1 ? s1[1] : (p2 ? m : s2[1]);
                i2[1] = p1 ? i1[1] : (p2 ? mc : i2[1]);
                i1[1] = p1 ? mc : i1[1];
                s1[1] = p1 ? m  : s1[1];
            }
        }
    }

    // quad-merge top-2 across the 4 lanes sharing each row
    #pragma unroll
    for (int sl = 0; sl < 2; sl++) {
        #pragma unroll
        for (int off = 1; off <= 2; off <<= 1) {
            float os1 = __shfl_xor_sync(0xFFFFFFFF, s1[sl], off);
            int   oi1 = __shfl_xor_sync(0xFFFFFFFF, i1[sl], off);
            float os2 = __shfl_xor_sync(0xFFFFFFFF, s2[sl], off);
            int   oi2 = __shfl_xor_sync(0xFFFFFFFF, i2[sl], off);
            if (sless(os1, oi1, s1[sl], i1[sl])) {
                if (sless(s1[sl], i1[sl], os2, oi2)) {
                    s2[sl] = s1[sl]; i2[sl] = i1[sl];
                } else {
                    s2[sl] = os2; i2[sl] = oi2;
                }
                s1[sl] = os1; i1[sl] = oi1;
            } else if (sless(os1, oi1, s2[sl], i2[sl])) {
                s2[sl] = os1; i2[sl] = oi1;
            }
        }
    }
    int2* rowtab = (int2*)(smem + SMF_BUF);
    if (c0 == 0) {
        #pragma unroll
        for (int sl = 0; sl < 2; sl++)
            rowtab[wid * 16 + sl * 8 + r0] = make_int2(i1[sl], i2[sl]);
    }
    __syncthreads();

    // final per-row epilogue (threads 0..127): exact fp32 rescore of top-2
    long long* wl = (long long*)(smem + SMF_WL);
    if (tid < ROWS_CTA) {
        const int row = rowbase + tid;
        int ca = rowtab[tid].x, cb2 = rowtab[tid].y;
        const float4* xp = (const float4*)(xs + tid * XSTRIDE);
        float da = 0.f, db = 0.f;
        {
            const float4* ea = (const float4*)(g_et + (size_t)ca * D);
            const float4* eb = (const float4*)(g_et + (size_t)cb2 * D);
            #pragma unroll
            for (int i = 0; i < 16; i++) {
                float4 xv = xp[i], e1v = ea[i], e2v = eb[i];
                da = fmaf(xv.x, e1v.x, da); da = fmaf(xv.y, e1v.y, da);
                da = fmaf(xv.z, e1v.z, da); da = fmaf(xv.w, e1v.w, da);
                db = fmaf(xv.x, e2v.x, db); db = fmaf(xv.y, e2v.y, db);
                db = fmaf(xv.z, e2v.z, db); db = fmaf(xv.w, e2v.w, db);
            }
        }
        float sa = fmaf(-2.f, da, esq_s[ca]);
        float sb = fmaf(-2.f, db, esq_s[cb2]);
        int bi = sless(sb, cb2, sa, ca) ? cb2 : ca;

        float ls = 0.f;
        {
            const float4* ep = (const float4*)(g_et + (size_t)bi * D);
            float4* qp = (float4*)(out + OFF_QUANT + (size_t)row * D);
            #pragma unroll
            for (int i = 0; i < 16; i++) {
                float4 e = ep[i], xv = xp[i];
                qp[i] = e;
                float a0 = e.x - xv.x, a1 = e.y - xv.y;
                float a2 = e.z - xv.z, a3 = e.w - xv.w;
                ls = fmaf(a0, a0, ls); ls = fmaf(a1, a1, ls);
                ls = fmaf(a2, a2, ls); ls = fmaf(a3, a3, ls);
            }
        }
        #pragma unroll
        for (int off = 16; off > 0; off >>= 1)
            ls += __shfl_xor_sync(0xFFFFFFFF, ls, off);
        if (lane == 0)   // fixed-point warp partial -> smem (deterministic)
            wl[wid] = (long long)__float2ll_rn(ls * 16777216.0f);

        out[OFF_IDX + row] = (float)bi;
        out[OFF_ENC + (size_t)row * K + bi] = 1.0f;
    }
    __syncthreads();

    // tid 0: single fenced g_loss add, then last-CTA-done finalize
    if (tid == 0) {
        long long csum = wl[0] + wl[1] + wl[2] + wl[3];
        atomicAdd(&g_loss, (unsigned long long)csum);
        __threadfence();
        unsigned int old = atomicInc(&g_done, NBLK - 1);
        if (old == NBLK - 1) {
            unsigned long long tot = atomicAdd(&g_loss, 0ull);
            out[OFF_LOSS] = (float)((double)tot
                          / (16777216.0 * (double)N_ROWS * (double)D));
        }
    }
}

extern "C" void kernel_launch(void* const* d_in, const int* in_sizes, int n_in,
                              void* d_out, int out_size) {
    const float* x   = (const float*)d_in[0];   // [8,4096,64]
    const float* emb = (const float*)d_in[1];   // [64,1024]
    float* out = (float*)d_out;

    cudaFuncSetAttribute(vq_mma, cudaFuncAttributeMaxDynamicSharedMemorySize,
                         SMEM_SZ);
    prep_all<<<16, 256>>>(emb);
    vq_mma<<<NBLK, NTHR, SMEM_SZ>>>(x, out);
}

// round 13
// speedup vs baseline: 1.0772x; 1.0285x over previous
#include <cuda_runtime.h>
#include <cuda_fp16.h>
#include <cstdint>

#define N_ROWS 32768
#define D      64
#define K      1024
#define NTHR   256                     // 8 warps per CTA
#define ROWS_CTA 128
#define NBLK   (N_ROWS / ROWS_CTA)     // 256 CTAs (2/SM -> one wave)
#define NCH    64
#define NCHUNK (K / NCH)               // 16

#define OFF_QUANT 0
#define OFF_ENC   ((size_t)N_ROWS * D)
#define OFF_IDX   (OFF_ENC + (size_t)N_ROWS * K)
#define OFF_LOSS  (OFF_IDX + (size_t)N_ROWS)

// smem (floats): esq[1024] | buf0[3072] | buf1[3072] | xtile[128*68] | tab[128] | wl[16]
#define SMF_ESQ  0
#define SMF_BUF  1024
#define SMF_X    (1024 + 6144)
#define XSTRIDE  68
#define SMF_TAB  (SMF_X + 128 * XSTRIDE)
#define SMF_WL   (SMF_TAB + 128)
#define SMEM_SZ  ((SMF_WL + 16) * 4)             // 64064 B -> 2 CTAs/SM

// Packed per-chunk B block (12KB each, 16 chunks):
//   u4[  0..255]  hi ks0|ks1   [nt(8)][lane(32)] -> uint4
//   u4[256..511]  hi ks2|ks3
//   u2[1024..1279] esq hi (ks4 pseudo-dim)   (byte 8192)
//   u2[1280..1535] esq lo                    (byte 10240)
__device__ uint4 g_bpk[NCHUNK * 768];
__device__ float g_et [K * D];           // exact emb^T [k][d]
__device__ float g_esq[K];
__device__ unsigned long long g_loss;
__device__ unsigned int g_done;          // wraps to 0 each launch (atomicInc)

__device__ __forceinline__ uint32_t smem_u32(const void* p) {
    uint32_t a;
    asm("{ .reg .u64 t; cvta.to.shared.u64 t, %1; cvt.u32.u64 %0, t; }"
        : "=r"(a) : "l"(p));
    return a;
}
__device__ __forceinline__ uint32_t packh2(float a, float b) {
    __half2 h = __floats2half2_rn(a, b);   // a -> low half (smaller index)
    return *(uint32_t*)&h;
}

#define CP16(dst, src) asm volatile( \
    "cp.async.cg.shared.global [%0], [%1], 16;" :: "r"(dst), "l"(src) : "memory")
#define CP_COMMIT() asm volatile("cp.async.commit_group;" ::: "memory")
#define CP_WAIT0()  asm volatile("cp.async.wait_group 0;" ::: "memory")

#define LDS64(r0, r1, addr) asm volatile( \
    "ld.shared.v2.b32 {%0,%1}, [%2];" : "=r"(r0), "=r"(r1) : "r"(addr))
#define LDS128(r0, r1, r2, r3, addr) asm volatile( \
    "ld.shared.v4.b32 {%0,%1,%2,%3}, [%4];" \
    : "=r"(r0), "=r"(r1), "=r"(r2), "=r"(r3) : "r"(addr))

#define MMAF16(Cp, Ap, B0, B1) asm volatile( \
    "mma.sync.aligned.m16n8k16.row.col.f32.f16.f16.f32 " \
    "{%0,%1,%2,%3},{%4,%5,%6,%7},{%8,%9},{%0,%1,%2,%3};" \
    : "+f"((Cp)[0]), "+f"((Cp)[1]), "+f"((Cp)[2]), "+f"((Cp)[3]) \
    : "r"((Ap)[0]), "r"((Ap)[1]), "r"((Ap)[2]), "r"((Ap)[3]), \
      "r"(B0), "r"(B1))

// ---------------- prep: e^T, ||e||^2, packed fp16-hi fragments -------------
__global__ void prep_all(const float* __restrict__ emb) {
    int idx = blockIdx.x * blockDim.x + threadIdx.x;   // 0..4095
    if (idx == 0) g_loss = 0ull;
    int lane = idx & 31;
    int ntg  = idx >> 5;                 // 0..127 global n-tile
    int c    = ntg >> 3, nt = ntg & 7;
    int cw   = ntg * 8 + (lane >> 2);

    uint4 hi01, hi23;
    #pragma unroll
    for (int ks = 0; ks < 4; ks++) {
        int d0 = ks * 16 + (lane & 3) * 2;
        float v0 = emb[(d0    ) * K + cw];
        float v1 = emb[(d0 + 1) * K + cw];
        float v2 = emb[(d0 + 8) * K + cw];
        float v3 = emb[(d0 + 9) * K + cw];
        uint32_t hu0 = packh2(v0, v1), hu1 = packh2(v2, v3);
        if (ks == 0)      { hi01.x = hu0; hi01.y = hu1; }
        else if (ks == 1) { hi01.z = hu0; hi01.w = hu1; }
        else if (ks == 2) { hi23.x = hu0; hi23.y = hu1; }
        else              { hi23.z = hu0; hi23.w = hu1; }
    }
    int slot = c * 768 + nt * 32 + lane;
    g_bpk[slot      ] = hi01;
    g_bpk[slot + 256] = hi23;

    // ks4: esq pseudo-dim (hi+lo split -> exact); lane&3==0 carries data
    {
        uint2 hv = make_uint2(0, 0), lv = make_uint2(0, 0);
        if ((lane & 3) == 0) {
            float esq = 0.f;
            #pragma unroll
            for (int d = 0; d < D; d++) {
                float v = emb[d * K + cw];
                esq = fmaf(v, v, esq);
            }
            float eh = __half2float(__float2half_rn(esq));
            hv.x = packh2(eh, 0.f);
            lv.x = packh2(esq - eh, 0.f);
        }
        uint2* p2 = (uint2*)g_bpk;
        p2[c * 1536 + 1024 + nt * 32 + lane] = hv;
        p2[c * 1536 + 1280 + nt * 32 + lane] = lv;
    }
    // exact transpose + norms (first 1024 threads)
    if (idx < K) {
        float s = 0.f;
        #pragma unroll
        for (int d = 0; d < D; d++) {
            float v = emb[d * K + idx];
            g_et[idx * D + d] = v;
            s = fmaf(v, v, s);
        }
        g_esq[idx] = s;
    }
}

// ---------------- staging: 12KB linear copy per chunk ----------------------
__device__ __forceinline__ void stage_chunk(uint32_t bufb, int c, int tid) {
    const char* s = (const char*)(g_bpk + (size_t)c * 768);
    #pragma unroll
    for (int i = 0; i < 3; i++) {
        uint32_t o = (uint32_t)(i * NTHR + tid) * 16;
        CP16(bufb + o, s + o);
    }
    CP_COMMIT();
}

__device__ __forceinline__ bool sless(float s, int i, float S, int I) {
    return (s < S) || (s == S && i < I);
}

// exact fp32 score of codeword k against x row in smem (stride XSTRIDE)
__device__ __forceinline__ float exact_score(const float4* __restrict__ xp,
                                             int k, const float* esq_s) {
    const float4* ep = (const float4*)(g_et + (size_t)k * D);
    float d0 = 0.f;
    #pragma unroll
    for (int i = 0; i < 16; i++) {
        float4 xv = xp[i], ev = ep[i];
        d0 = fmaf(xv.x, ev.x, d0); d0 = fmaf(xv.y, ev.y, d0);
        d0 = fmaf(xv.z, ev.z, d0); d0 = fmaf(xv.w, ev.w, d0);
    }
    return fmaf(-2.f, d0, esq_s[k]);
}

// ---------------- main ------------------------------------------------------
__global__ __launch_bounds__(NTHR, 2) void vq_mma(const float* __restrict__ x,
                                                  float* __restrict__ out) {
    extern __shared__ __align__(16) float smem[];
    const uint32_t smb = smem_u32(smem);
    float* esq_s = smem + SMF_ESQ;
    float* xs    = smem + SMF_X;
    const int tid  = threadIdx.x;
    const int wid  = tid >> 5, lane = tid & 31;
    const int r0   = lane >> 2, c0 = lane & 3;
    const int rowbase = blockIdx.x * ROWS_CTA;

    stage_chunk(smb + SMF_BUF * 4, 0, tid);

    #pragma unroll
    for (int i = 0; i < K / NTHR; i++)
        esq_s[i * NTHR + tid] = g_esq[i * NTHR + tid];

    // stage x tile (raw floats, stride 68 => conflict-free row reads)
    {
        const float4* xg = (const float4*)(x + (size_t)rowbase * D);
        #pragma unroll
        for (int i = 0; i < 8; i++) {
            int idx = i * NTHR + tid;
            int r = idx >> 4, d4 = idx & 15;
            *(float4*)(xs + r * XSTRIDE + d4 * 4) = xg[idx];
        }
    }
    __syncthreads();

    // A fragments: y = -2x, split y = y0 + y1 (fp16); +ks4 pseudo-dim (y=1).
    uint32_t ay0[20], ay1[16];
    #pragma unroll
    for (int ks = 0; ks < 4; ks++)
        #pragma unroll
        for (int p = 0; p < 4; p++) {
            int r = wid * 16 + r0 + (p & 1) * 8;
            int d = ks * 16 + c0 * 2 + (p >> 1) * 8;
            float va = -2.f * xs[r * XSTRIDE + d];
            float vb = -2.f * xs[r * XSTRIDE + d + 1];
            float ha = __half2float(__float2half_rn(va));
            float hb = __half2float(__float2half_rn(vb));
            ay0[ks * 4 + p] = packh2(ha, hb);
            ay1[ks * 4 + p] = packh2(va - ha, vb - hb);
        }
    {
        uint32_t one = (c0 == 0) ? packh2(1.f, 0.f) : 0u;
        ay0[16] = one; ay0[17] = one; ay0[18] = 0u; ay0[19] = 0u;
    }

    // per-slot approx top-2; slot 0 = row r0, slot 1 = row r0+8
    float s1[2], s2[2];
    int   i1[2], i2[2];
    #pragma unroll
    for (int s = 0; s < 2; s++) { s1[s] = s2[s] = 3.4e38f; i1[s] = i2[s] = 0; }

    #pragma unroll 1
    for (int c = 0; c < NCHUNK; c++) {
        CP_WAIT0();
        __syncthreads();   // buf[c] visible; prior reads of other buf done
        if (c + 1 < NCHUNK)
            stage_chunk(smb + (SMF_BUF + ((c + 1) & 1) * 3072) * 4, c + 1, tid);

        // encodings zero-fill for this chunk's 64 columns
        {
            float4 z = make_float4(0.f, 0.f, 0.f, 0.f);
            float* enc = out + OFF_ENC + (size_t)rowbase * K + (size_t)c * NCH;
            #pragma unroll
            for (int j = 0; j < 8; j++) {
                int idx = j * NTHR + tid;
                *(float4*)(enc + (size_t)(idx >> 4) * K + (idx & 15) * 4) = z;
            }
        }

        const uint32_t bufb = smb + (SMF_BUF + (c & 1) * 3072) * 4;

        // nt pairs: two independent accumulator chains
        #pragma unroll
        for (int nt = 0; nt < 8; nt += 2) {
            uint32_t Ah01[4], Ah23[4], Ah4[2], Al4[2];
            uint32_t Bh01[4], Bh23[4], Bh4[2], Bl4[2];
            {
                uint32_t a16 = bufb + (uint32_t)(((nt    ) * 32 + lane) * 16);
                uint32_t b16 = bufb + (uint32_t)(((nt + 1) * 32 + lane) * 16);
                uint32_t a8  = bufb + (uint32_t)(((nt    ) * 32 + lane) * 8);
                uint32_t b8  = bufb + (uint32_t)(((nt + 1) * 32 + lane) * 8);
                LDS128(Ah01[0], Ah01[1], Ah01[2], Ah01[3], a16);
                LDS128(Bh01[0], Bh01[1], Bh01[2], Bh01[3], b16);
                LDS128(Ah23[0], Ah23[1], Ah23[2], Ah23[3], a16 + 4096);
                LDS128(Bh23[0], Bh23[1], Bh23[2], Bh23[3], b16 + 4096);
                LDS64(Ah4[0], Ah4[1], a8 + 8192);
                LDS64(Bh4[0], Bh4[1], b8 + 8192);
                LDS64(Al4[0], Al4[1], a8 + 10240);
                LDS64(Bl4[0], Bl4[1], b8 + 10240);
            }
            float C0[4] = {0.f, 0.f, 0.f, 0.f};
            float C1[4] = {0.f, 0.f, 0.f, 0.f};
            MMAF16(C0, ay0 + 0,  Ah01[0], Ah01[1]);   // ks0
            MMAF16(C1, ay0 + 0,  Bh01[0], Bh01[1]);
            MMAF16(C0, ay1 + 0,  Ah01[0], Ah01[1]);
            MMAF16(C1, ay1 + 0,  Bh01[0], Bh01[1]);
            MMAF16(C0, ay0 + 4,  Ah01[2], Ah01[3]);   // ks1
            MMAF16(C1, ay0 + 4,  Bh01[2], Bh01[3]);
            MMAF16(C0, ay1 + 4,  Ah01[2], Ah01[3]);
            MMAF16(C1, ay1 + 4,  Bh01[2], Bh01[3]);
            MMAF16(C0, ay0 + 8,  Ah23[0], Ah23[1]);   // ks2
            MMAF16(C1, ay0 + 8,  Bh23[0], Bh23[1]);
            MMAF16(C0, ay1 + 8,  Ah23[0], Ah23[1]);
            MMAF16(C1, ay1 + 8,  Bh23[0], Bh23[1]);
            MMAF16(C0, ay0 + 12, Ah23[2], Ah23[3]);   // ks3
            MMAF16(C1, ay0 + 12, Bh23[2], Bh23[3]);
            MMAF16(C0, ay1 + 12, Ah23[2], Ah23[3]);
            MMAF16(C1, ay1 + 12, Bh23[2], Bh23[3]);
            MMAF16(C0, ay0 + 16, Ah4[0],  Ah4[1]);    // ks4 esq hi
            MMAF16(C1, ay0 + 16, Bh4[0],  Bh4[1]);
            MMAF16(C0, ay0 + 16, Al4[0],  Al4[1]);    // ks4 esq lo
            MMAF16(C1, ay0 + 16, Bl4[0],  Bl4[1]);

            // approx pair-then-insert top-2 (cols ascending, strict <)
            int cbA = c * NCH + nt * 8 + c0 * 2;
            int cbB = cbA + 8;
            {
                float m = fminf(C0[0], C0[1]);
                int  mc = cbA + ((C0[1] < C0[0]) ? 1 : 0);
                bool p1 = m < s1[0], p2 = m < s2[0];
                s2[0] = p1 ? s1[0] : (p2 ? m : s2[0]);
                i2[0] = p1 ? i1[0] : (p2 ? mc : i2[0]);
                i1[0] = p1 ? mc : i1[0];
                s1[0] = p1 ? m  : s1[0];
            }
            {
                float m = fminf(C0[2], C0[3]);
                int  mc = cbA + ((C0[3] < C0[2]) ? 1 : 0);
                bool p1 = m < s1[1], p2 = m < s2[1];
                s2[1] = p1 ? s1[1] : (p2 ? m : s2[1]);
                i2[1] = p1 ? i1[1] : (p2 ? mc : i2[1]);
                i1[1] = p1 ? mc : i1[1];
                s1[1] = p1 ? m  : s1[1];
            }
            {
                float m = fminf(C1[0], C1[1]);
                int  mc = cbB + ((C1[1] < C1[0]) ? 1 : 0);
                bool p1 = m < s1[0], p2 = m < s2[0];
                s2[0] = p1 ? s1[0] : (p2 ? m : s2[0]);
                i2[0] = p1 ? i1[0] : (p2 ? mc : i2[0]);
                i1[0] = p1 ? mc : i1[0];
                s1[0] = p1 ? m  : s1[0];
            }
            {
                float m = fminf(C1[2], C1[3]);
                int  mc = cbB + ((C1[3] < C1[2]) ? 1 : 0);
                bool p1 = m < s1[1], p2 = m < s2[1];
                s2[1] = p1 ? s1[1] : (p2 ? m : s2[1]);
                i2[1] = p1 ? i1[1] : (p2 ? mc : i2[1]);
                i1[1] = p1 ? mc : i1[1];
                s1[1] = p1 ? m  : s1[1];
            }
        }
    }

    // ---- exact rescue: rescore BOTH per-lane candidates, then quad-merge ----
    int* rowtab = (int*)(smem + SMF_TAB);
    #pragma unroll
    for (int sl = 0; sl < 2; sl++) {
        int r = wid * 16 + sl * 8 + r0;
        const float4* xp = (const float4*)(xs + r * XSTRIDE);
        float ea = exact_score(xp, i1[sl], esq_s);
        float eb = exact_score(xp, i2[sl], esq_s);
        float bs; int bidx;
        if (sless(eb, i2[sl], ea, i1[sl])) { bs = eb; bidx = i2[sl]; }
        else                               { bs = ea; bidx = i1[sl]; }
        #pragma unroll
        for (int off = 1; off <= 2; off <<= 1) {
            float os = __shfl_xor_sync(0xFFFFFFFF, bs, off);
            int   oi = __shfl_xor_sync(0xFFFFFFFF, bidx, off);
            if (sless(os, oi, bs, bidx)) { bs = os; bidx = oi; }
        }
        if (c0 == 0) rowtab[r] = bidx;
    }
    __syncthreads();

    // final per-row epilogue (threads 0..127): outputs + loss
    long long* wl = (long long*)(smem + SMF_WL);
    if (tid < ROWS_CTA) {
        const int row = rowbase + tid;
        const int bi  = rowtab[tid];
        const float4* xp = (const float4*)(xs + tid * XSTRIDE);
        float ls = 0.f;
        {
            const float4* ep = (const float4*)(g_et + (size_t)bi * D);
            float4* qp = (float4*)(out + OFF_QUANT + (size_t)row * D);
            #pragma unroll
            for (int i = 0; i < 16; i++) {
                float4 e = ep[i], xv = xp[i];
                qp[i] = e;
                float a0 = e.x - xv.x, a1 = e.y - xv.y;
                float a2 = e.z - xv.z, a3 = e.w - xv.w;
                ls = fmaf(a0, a0, ls); ls = fmaf(a1, a1, ls);
                ls = fmaf(a2, a2, ls); ls = fmaf(a3, a3, ls);
            }
        }
        #pragma unroll
        for (int off = 16; off > 0; off >>= 1)
            ls += __shfl_xor_sync(0xFFFFFFFF, ls, off);
        if (lane == 0)   // fixed-point warp partial -> smem (deterministic)
            wl[wid] = (long long)__float2ll_rn(ls * 16777216.0f);

        out[OFF_IDX + row] = (float)bi;
        out[OFF_ENC + (size_t)row * K + bi] = 1.0f;
    }
    __syncthreads();

    // tid 0: single fenced g_loss add, then last-CTA-done finalize
    if (tid == 0) {
        long long csum = wl[0] + wl[1] + wl[2] + wl[3];
        atomicAdd(&g_loss, (unsigned long long)csum);
        __threadfence();
        unsigned int old = atomicInc(&g_done, NBLK - 1);
        if (old == NBLK - 1) {
            unsigned long long tot = atomicAdd(&g_loss, 0ull);
            out[OFF_LOSS] = (float)((double)tot
                          / (16777216.0 * (double)N_ROWS * (double)D));
        }
    }
}

extern "C" void kernel_launch(void* const* d_in, const int* in_sizes, int n_in,
                              void* d_out, int out_size) {
    const float* x   = (const float*)d_in[0];   // [8,4096,64]
    const float* emb = (const float*)d_in[1];   // [64,1024]
    float* out = (float*)d_out;

    cudaFuncSetAttribute(vq_mma, cudaFuncAttributeMaxDynamicSharedMemorySize,
                         SMEM_SZ);
    prep_all<<<16, 256>>>(emb);
    vq_mma<<<NBLK, NTHR, SMEM_SZ>>>(x, out);
}